// round 9
// baseline (speedup 1.0000x reference)
#include <cuda_runtime.h>
#include <cstdint>

// Output: (BATCH=256, SEQ=512, DIM=64) fp32 = 33.5 MB.
// inputs: (256,512) fp32; tables: (3,100000,64) fp32; table_ids: (512) int32.
//
// Pipeline redesign:
//  - gathers via cp.async (LDGSTS.128) global->smem: no result registers,
//    deep MLP for free.
//  - output written by ONE cp.async.bulk (TMA) 32KB smem->global per block:
//    stores leave the per-warp LSU path entirely.

#define BATCH 256
#define SEQ   512
#define DIM   64
#define VOCAB 100000
#define ROWS_PER_BLK 128
#define THREADS 256
#define U 8                       // float4 slots per thread: 128*16/256

#define TILE_BYTES (ROWS_PER_BLK * DIM * 4)   // 32768

__global__ void __launch_bounds__(THREADS)
emb_gather_kernel(const float* __restrict__ inputs,
                  const float* __restrict__ tables,
                  const int*   __restrict__ table_ids,
                  float*       __restrict__ out)
{
    __shared__ __align__(128) float4 s_tile[ROWS_PER_BLK * (DIM / 4)]; // 32KB
    __shared__ int   s_off[ROWS_PER_BLK];
    __shared__ float s_val[ROWS_PER_BLK];

    const int tid  = threadIdx.x;
    const int row0 = blockIdx.x * ROWS_PER_BLK;

    // ---- Phase 1: per-row descriptors ----
    if (tid < ROWS_PER_BLK) {
        int row = row0 + tid;
        int s   = row & (SEQ - 1);
        float v = __ldg(&inputs[row]);
        int  tb = __ldg(&table_ids[s]);
        s_val[tid] = v;
        s_off[tid] = (tb >= 0) ? (tb * VOCAB + (int)v) * (DIM / 4) : -1;
    }
    __syncthreads();

    // ---- Phase 2: cp.async gathers into the output tile ----
    const float4* t4 = (const float4*)tables;
    #pragma unroll
    for (int k = 0; k < U; k++) {
        int j    = k * THREADS + tid;
        int rl   = j >> 4;
        int lane = j & 15;
        int off  = s_off[rl];
        unsigned sdst;
        asm("{ .reg .u64 t; cvta.to.shared.u64 t, %1; cvt.u32.u64 %0, t; }"
            : "=r"(sdst) : "l"(s_tile + j));
        if (off >= 0) {
            const float4* src = t4 + off + lane;
            asm volatile("cp.async.cg.shared.global [%0], [%1], 16;"
                         :: "r"(sdst), "l"(src) : "memory");
        } else {
            float v = s_val[rl];
            float4 f = make_float4(v, v, v, v);
            asm volatile("st.shared.v4.f32 [%0], {%1,%2,%3,%4};"
                         :: "r"(sdst), "f"(f.x), "f"(f.y), "f"(f.z), "f"(f.w)
                         : "memory");
        }
    }
    asm volatile("cp.async.commit_group;" ::: "memory");
    asm volatile("cp.async.wait_group 0;" ::: "memory");
    __syncthreads();

    // ---- Phase 3: one bulk TMA store of the whole 32KB tile ----
    if (tid == 0) {
        asm volatile("fence.proxy.async.shared::cta;" ::: "memory");
        unsigned ssrc;
        asm("{ .reg .u64 t; cvta.to.shared.u64 t, %1; cvt.u32.u64 %0, t; }"
            : "=r"(ssrc) : "l"(s_tile));
        const float* gdst = out + (size_t)row0 * DIM;
        asm volatile("cp.async.bulk.global.shared::cta.bulk_group [%0], [%1], %2;"
                     :: "l"(gdst), "r"(ssrc), "n"(TILE_BYTES) : "memory");
        asm volatile("cp.async.bulk.commit_group;" ::: "memory");
        asm volatile("cp.async.bulk.wait_group 0;" ::: "memory");
    }
}

extern "C" void kernel_launch(void* const* d_in, const int* in_sizes, int n_in,
                              void* d_out, int out_size)
{
    const float* inputs    = (const float*)d_in[0];
    const float* tables    = (const float*)d_in[1];
    const int*   table_ids = (const int*)d_in[2];
    float*       out       = (float*)d_out;

    int blocks = (BATCH * SEQ) / ROWS_PER_BLK;   // 1024
    emb_gather_kernel<<<blocks, THREADS>>>(inputs, tables, table_ids, out);
}